// round 16
// baseline (speedup 1.0000x reference)
#include <cuda_runtime.h>
#include <cuda_fp16.h>
#include <math.h>
#include <stdint.h>

#define S_SP 131072      // 32*64*64
#define C_IN 320
#define C_MID 160
#define NB 2
#define TN 128           // spatial tile per CTA
#define NT (S_SP / TN)   // 1024 tiles per (n,t)
#define NPT (NT * 2)     // stat partials per channel (2 warp-halves per tile)
#define KC 32
#define NCH (C_IN / KC)  // 10

// ---------------- scratch ----------------
__device__ __half d_y[(size_t)2 * NB * C_MID * S_SP];  // pre-norm conv outputs (fp16)
__device__ float d_psum[2 * NB * C_MID * NPT];
__device__ float d_psq [2 * NB * C_MID * NPT];
__device__ float d_mean[2 * NB * C_MID];
__device__ float d_rstd[2 * NB * C_MID];
__device__ float d_Wpack[2 * NCH * C_MID * 36];        // W packed [t][chunk][ch][36] (pad 32..35 = 0)
__device__ float d_pv[NB * S_SP];                      // psi gate values (1MB, L2-resident)

// smem: W stages x2 (23040B each) + B stages x3 (17408B each).
// SA=36: A-load bank = lq*4+tig (perfect permutation). SB=136 (==8 mod 32):
// B-load bank = tig*8+lq (perfect permutation).
#define SA 36
#define SB 136
#define W_BYTES (C_MID * SA * 4)            // 23040
#define B_BYTES (KC * SB * 4)               // 17408
#define B_TX    (KC * TN * 4)               // 16384 actually transferred per B stage
#define OFF_STG 64
#define OFF_B   (OFF_STG + 2 * W_BYTES)     // 46144
#define SMEM_BYTES (OFF_B + 3 * B_BYTES)    // 98368

// ---------------- helpers ----------------
__device__ __forceinline__ uint32_t smem_u32(const void* p) {
    uint32_t a;
    asm("{ .reg .u64 t; cvta.to.shared.u64 t, %1; cvt.u32.u64 %0, t; }" : "=r"(a) : "l"(p));
    return a;
}
#define MBAR_INIT(a, cnt) asm volatile("mbarrier.init.shared.b64 [%0], %1;" :: "r"(a), "r"(cnt) : "memory")
#define MBAR_EXPECT(a, bytes) \
    asm volatile("mbarrier.arrive.expect_tx.shared.b64 _, [%0], %1;" :: "r"(a), "r"(bytes) : "memory")
#define MBAR_WAIT(mb, ph) do {                                                          \
    uint32_t _m = (mb), _p = (ph), _d;                                                  \
    asm volatile("{ .reg .pred p; mbarrier.try_wait.parity.acquire.cta.shared::cta.b64 p, [%1], %2; selp.b32 %0,1,0,p; }" \
        : "=r"(_d) : "r"(_m), "r"(_p) : "memory");                                      \
    if (!_d) {                                                                          \
        asm volatile("{ .reg .pred P1; WL_%=: mbarrier.try_wait.parity.acquire.cta.shared::cta.b64 P1, [%0], %1, 0x989680; @P1 bra.uni WD_%=; bra.uni WL_%=; WD_%=: }" \
            :: "r"(_m), "r"(_p) : "memory");                                            \
    }                                                                                   \
} while (0)
#define BULK_CP(dst, src, bytes, mbar) \
    asm volatile("cp.async.bulk.shared::cta.global.mbarrier::complete_tx::bytes [%0], [%1], %2, [%3];" \
        :: "r"(dst), "l"(src), "r"(bytes), "r"(mbar) : "memory")

// HMMA.TF32 ignores the low 13 mantissa bits: raw fp32 bit patterns are valid
// tf32 operands (truncation). No cvt needed.
#define MMA(c, a, b) asm volatile( \
    "mma.sync.aligned.m16n8k8.row.col.f32.tf32.tf32.f32 " \
    "{%0,%1,%2,%3}, {%4,%5,%6,%7}, {%8,%9}, {%0,%1,%2,%3};" \
    : "+f"((c)[0]), "+f"((c)[1]), "+f"((c)[2]), "+f"((c)[3]) \
    : "r"((a)[0]), "r"((a)[1]), "r"((a)[2]), "r"((a)[3]), "r"((b)[0]), "r"((b)[1]))

// Branchless fast ELU: v>0 -> v (exp(0)-1 == 0 exactly); v<=0 -> exp(v)-1.
__device__ __forceinline__ float elu1(float v) {
    return fmaxf(v, 0.0f) + (__expf(fminf(v, 0.0f)) - 1.0f);
}

// ======================= pass 0: pack W with smem-friendly padding =======================
__global__ void pack_w_kernel(const float* __restrict__ Wg, const float* __restrict__ Wx) {
    const int total = 2 * NCH * C_MID * 36;
    for (int idx = blockIdx.x * blockDim.x + threadIdx.x; idx < total; idx += gridDim.x * blockDim.x) {
        int t  = idx / (NCH * C_MID * 36);
        int r0 = idx % (NCH * C_MID * 36);
        int c  = r0 / (C_MID * 36);
        int r  = r0 % (C_MID * 36);
        int ch = r / 36, kk = r % 36;
        const float* W = t ? Wx : Wg;
        d_Wpack[idx] = (kk < 32) ? W[ch * C_IN + c * KC + kk] : 0.0f;
    }
}

// ======================= pass 1: tf32 mma.sync GEMM + per-tile stats =======================
// grid (1024, n=2, t=2), 320 threads (10 warps: 5 M x 2 N), warp tile 32ch x 64sp.
// Chunk top: sync (buffers free) -> issue stages -> wait data -> compute, keeping
// stage issue and the W-wait off the critical path. Bias omitted (cancels in IN).
__global__ void __launch_bounds__(320, 2)
gemm_mma_kernel(const float* __restrict__ g, const float* __restrict__ x) {
    extern __shared__ float sm[];
    const uint32_t smb = smem_u32(sm);
    const int tid = threadIdx.x;
    const int wid = tid >> 5, lane = tid & 31;
    const int tile = blockIdx.x, n = blockIdx.y, t = blockIdx.z;
    const int s0 = tile * TN;

    const float* Wp  = d_Wpack + t * NCH * C_MID * 36;                // packed W
    const float* inb = (t ? x : g) + (size_t)n * C_IN * S_SP + s0;    // [320][S]

    const int wm = wid >> 1, wn = wid & 1;
    const int lq = lane >> 2, tig = lane & 3;

    float acc[2][8][4];
#pragma unroll
    for (int m = 0; m < 2; m++)
#pragma unroll
        for (int nf = 0; nf < 8; nf++)
#pragma unroll
            for (int j = 0; j < 4; j++) acc[m][nf][j] = 0.0f;

    // mbarriers: W at +0,+8 ; B at +16,+24,+32
    if (tid == 0) {
        MBAR_INIT(smb + 0, 1);  MBAR_INIT(smb + 8, 1);
        MBAR_INIT(smb + 16, 1); MBAR_INIT(smb + 24, 1); MBAR_INIT(smb + 32, 1);
    }
    __syncthreads();

    auto stage_w = [&](int c) {
        const uint32_t mb = smb + (c & 1) * 8;
        MBAR_EXPECT(mb, W_BYTES);
        BULK_CP(smb + OFF_STG + (c & 1) * W_BYTES, (const void*)(Wp + c * C_MID * 36), W_BYTES, mb);
    };
    auto stage_b = [&](int c) {
        const uint32_t mb = smb + 16 + (c % 3) * 8;
        const uint32_t bb = smb + OFF_B + (c % 3) * B_BYTES;
        MBAR_EXPECT(mb, B_TX);
        const float* src = inb + (size_t)(c * KC) * S_SP;
#pragma unroll
        for (int k = 0; k < KC; k++)
            BULK_CP(bb + k * (SB * 4), (const void*)(src + (size_t)k * S_SP), TN * 4, mb);
    };

    if (tid == 0) { stage_w(0); stage_b(0); stage_b(1); }

#pragma unroll
    for (int c = 0; c < NCH; c++) {
        __syncthreads();                                      // all warps past compute(c-1): bufs free
        if (tid == 0) {
            if (c + 1 < NCH) stage_w(c + 1);                  // overwrites W buf (c-1)&1: free
            if (c + 2 < NCH) stage_b(c + 2);                  // overwrites B buf (c-1)%3: free
        }
        MBAR_WAIT(smb + (c & 1) * 8, (c >> 1) & 1);          // W(c) arrived
        MBAR_WAIT(smb + 16 + (c % 3) * 8, (c / 3) & 1);      // B(c) arrived

        const float* sa = (const float*)((const char*)sm + OFF_STG + (c & 1) * W_BYTES);
        const float* sb = (const float*)((const char*)sm + OFF_B + (c % 3) * B_BYTES);

#pragma unroll
        for (int ks = 0; ks < 4; ks++) {
            const int kk = ks * 8;
            uint32_t a[2][4];
#pragma unroll
            for (int m = 0; m < 2; m++) {
                int r0 = wm * 32 + m * 16 + lq;
                a[m][0] = __float_as_uint(sa[r0 * SA + kk + tig]);
                a[m][1] = __float_as_uint(sa[(r0 + 8) * SA + kk + tig]);
                a[m][2] = __float_as_uint(sa[r0 * SA + kk + tig + 4]);
                a[m][3] = __float_as_uint(sa[(r0 + 8) * SA + kk + tig + 4]);
            }
#pragma unroll
            for (int nf = 0; nf < 8; nf++) {
                int col = wn * 64 + nf * 8 + lq;
                uint32_t b[2];
                b[0] = __float_as_uint(sb[(kk + tig) * SB + col]);
                b[1] = __float_as_uint(sb[(kk + 4 + tig) * SB + col]);
                MMA(acc[0][nf], a[0], b);
                MMA(acc[1][nf], a[1], b);
            }
        }
    }

    // ---- epilogue: store y as fp16 (half2) + per-row partial fp32 stats ----
    float rsum[4] = {0.f, 0.f, 0.f, 0.f};
    float rsq [4] = {0.f, 0.f, 0.f, 0.f};
#pragma unroll
    for (int m = 0; m < 2; m++) {
        const int r0 = wm * 32 + m * 16 + lq;
        const size_t base = (size_t)((t * NB + n) * C_MID) * S_SP + s0 + wn * 64 + 2 * tig;
        __half* y0 = d_y + base + (size_t)r0 * S_SP;
        __half* y1 = d_y + base + (size_t)(r0 + 8) * S_SP;
#pragma unroll
        for (int nf = 0; nf < 8; nf++) {
            float v0 = acc[m][nf][0], v1 = acc[m][nf][1];
            float v2 = acc[m][nf][2], v3 = acc[m][nf][3];
            *(__half2*)(y0 + nf * 8) = __floats2half2_rn(v0, v1);
            *(__half2*)(y1 + nf * 8) = __floats2half2_rn(v2, v3);
            rsum[2 * m]     += v0 + v1;
            rsq [2 * m]     += v0 * v0 + v1 * v1;
            rsum[2 * m + 1] += v2 + v3;
            rsq [2 * m + 1] += v2 * v2 + v3 * v3;
        }
    }
#pragma unroll
    for (int j = 0; j < 4; j++) {
        rsum[j] += __shfl_xor_sync(0xffffffffu, rsum[j], 1);
        rsum[j] += __shfl_xor_sync(0xffffffffu, rsum[j], 2);
        rsq [j] += __shfl_xor_sync(0xffffffffu, rsq [j], 1);
        rsq [j] += __shfl_xor_sync(0xffffffffu, rsq [j], 2);
    }
    if (tig == 0) {
#pragma unroll
        for (int j = 0; j < 4; j++) {
            int ch = wm * 32 + (j >> 1) * 16 + (j & 1) * 8 + lq;
            int idx = ((t * NB + n) * C_MID + ch) * NPT + tile * 2 + wn;
            d_psum[idx] = rsum[j];
            d_psq [idx] = rsq [j];
        }
    }
}

// ======================= pass 2: finalize mean / rstd =======================
__global__ void finalize_stats_kernel() {
    const int c = blockIdx.x, n = blockIdx.y, t = blockIdx.z;
    const int base = ((t * NB + n) * C_MID + c) * NPT;
    __shared__ float s1[256], s2[256];
    float a = 0.f, b = 0.f;
    for (int i = threadIdx.x; i < NPT; i += 256) { a += d_psum[base + i]; b += d_psq[base + i]; }
    s1[threadIdx.x] = a; s2[threadIdx.x] = b;
    __syncthreads();
    for (int st = 128; st; st >>= 1) {
        if (threadIdx.x < st) { s1[threadIdx.x] += s1[threadIdx.x + st]; s2[threadIdx.x] += s2[threadIdx.x + st]; }
        __syncthreads();
    }
    if (threadIdx.x == 0) {
        const float inv = 1.0f / (float)S_SP;
        float mean = s1[0] * inv;
        float var  = s2[0] * inv - mean * mean;
        d_mean[(t * NB + n) * C_MID + c] = mean;
        d_rstd[(t * NB + n) * C_MID + c] = rsqrtf(var + 1e-5f);
    }
}

// ======================= pass 3a: norm + elu + psi gate values =======================
// grid (S_SP/1024, n=2), 256 threads, 4 spatial/thread. One 8B load = 4 y values.
__global__ void __launch_bounds__(256)
psi_gate_kernel(const float* __restrict__ Wpsi, const float* __restrict__ bpsi) {
    const int n = blockIdx.y;
    const int s = (blockIdx.x * 256 + threadIdx.x) * 4;

    __shared__ float sWp[C_MID], sMg[C_MID], sRg[C_MID], sMx[C_MID], sRx[C_MID];
    if (threadIdx.x < C_MID) {
        int c = threadIdx.x;
        sWp[c] = Wpsi[c];
        sMg[c] = d_mean[(0 * NB + n) * C_MID + c];
        sRg[c] = d_rstd[(0 * NB + n) * C_MID + c];
        sMx[c] = d_mean[(1 * NB + n) * C_MID + c];
        sRx[c] = d_rstd[(1 * NB + n) * C_MID + c];
    }
    __syncthreads();

    const float b0 = bpsi[0];
    float z0 = b0, z1 = b0, z2 = b0, z3 = b0;
    const __half* yg = d_y + ((size_t)(0 * NB + n) * C_MID) * S_SP + s;
    const __half* yx = d_y + ((size_t)(1 * NB + n) * C_MID) * S_SP + s;
#pragma unroll 4
    for (int c = 0; c < C_MID; c++) {
        float2 rg4 = *(const float2*)(yg + (size_t)c * S_SP);   // 4 halves
        float2 rx4 = *(const float2*)(yx + (size_t)c * S_SP);
        float2 g01 = __half22float2(((const __half2*)&rg4)[0]);
        float2 g23 = __half22float2(((const __half2*)&rg4)[1]);
        float2 x01 = __half22float2(((const __half2*)&rx4)[0]);
        float2 x23 = __half22float2(((const __half2*)&rx4)[1]);
        float mg = sMg[c], rg = sRg[c], mx = sMx[c], rx = sRx[c], wp = sWp[c];
        z0 = fmaf(wp, elu1((g01.x - mg) * rg) + elu1((x01.x - mx) * rx), z0);
        z1 = fmaf(wp, elu1((g01.y - mg) * rg) + elu1((x01.y - mx) * rx), z1);
        z2 = fmaf(wp, elu1((g23.x - mg) * rg) + elu1((x23.x - mx) * rx), z2);
        z3 = fmaf(wp, elu1((g23.y - mg) * rg) + elu1((x23.y - mx) * rx), z3);
    }
    float4 p;
    p.x = __fdividef(1.0f, 1.0f + __expf(-z0));
    p.y = __fdividef(1.0f, 1.0f + __expf(-z1));
    p.z = __fdividef(1.0f, 1.0f + __expf(-z2));
    p.w = __fdividef(1.0f, 1.0f + __expf(-z3));
    *(float4*)&d_pv[(size_t)n * S_SP + s] = p;
}

// ======================= pass 3b: out = x * p (pure streaming, float4) =======================
// grid (S_SP/1024, C_IN, n=2), 256 threads, 4 floats/thread.
__global__ void __launch_bounds__(256)
mul_kernel(const float* __restrict__ x, float* __restrict__ out) {
    const int s = blockIdx.x * 1024 + threadIdx.x * 4;
    const int c = blockIdx.y;
    const int n = blockIdx.z;
    const size_t off = ((size_t)n * C_IN + c) * S_SP + s;
    float4 pv = *(const float4*)&d_pv[(size_t)n * S_SP + s];
    float4 xv = *(const float4*)&x[off];
    xv.x *= pv.x; xv.y *= pv.y; xv.z *= pv.z; xv.w *= pv.w;
    *(float4*)&out[off] = xv;
}

// ======================= launch =======================
extern "C" void kernel_launch(void* const* d_in, const int* in_sizes, int n_in,
                              void* d_out, int out_size) {
    const float* g    = (const float*)d_in[0];
    const float* x    = (const float*)d_in[1];
    const float* Wg   = (const float*)d_in[2];
    const float* Wx   = (const float*)d_in[4];
    const float* Wpsi = (const float*)d_in[6];
    const float* bpsi = (const float*)d_in[7];
    float* out = (float*)d_out;

    cudaFuncSetAttribute(gemm_mma_kernel, cudaFuncAttributeMaxDynamicSharedMemorySize, SMEM_BYTES);

    pack_w_kernel<<<80, 256>>>(Wg, Wx);
    gemm_mma_kernel<<<dim3(NT, NB, 2), 320, SMEM_BYTES>>>(g, x);
    finalize_stats_kernel<<<dim3(C_MID, NB, 2), 256>>>();
    psi_gate_kernel<<<dim3(S_SP / 1024, NB), 256>>>(Wpsi, bpsi);
    mul_kernel<<<dim3(S_SP / 1024, C_IN, NB), 256>>>(x, out);
}